// round 9
// baseline (speedup 1.0000x reference)
#include <cuda_runtime.h>
#include <cuda_fp16.h>
#include <cuda_bf16.h>
#include <math.h>

// ---------------------------------------------------------------------------
// GraphSAGE (3x SAGEConv mean + ReLU, softmax) on GB300 — round 9.
//  * FUSED layers: one kernel aggregates a 64-node tile (mean of neighbor P
//    rows + S + relu, split fp16 into SMEM) then runs the projection MMA for
//    the NEXT layer. h never touches gmem; gather overlaps MMA across the
//    2 co-resident CTAs per SM.
//  * gemm1 (X projection) and the final softmax aggregation stay standalone.
// ---------------------------------------------------------------------------

#define MAXN 100000
#define MAXE 1600000

__device__ int    g_deg[MAXN];
__device__ int    g_rowptr[MAXN + 1];
__device__ int    g_cursor[MAXN];
__device__ int    g_colidx[MAXE];
__device__ float  g_invdeg[MAXN];
__device__ float  g_S[(size_t)MAXN * 128];       // S1 (fp32, w128) / later S3 (w64)
__device__ __half g_P[(size_t)MAXN * 128];       // P1 (fp16, w128) / later P3 (w64)
__device__ __half g_buf2[(size_t)MAXN * 256];    // S2 (fp32 w64) + P2 (fp16 w64)

static __device__ __forceinline__ unsigned su32(const void* p) {
    return (unsigned)__cvta_generic_to_shared(p);
}

#define LDSM_X4(r, a)                                                          \
    asm volatile("ldmatrix.sync.aligned.m8n8.x4.shared.b16 {%0,%1,%2,%3}, [%4];" \
                 : "=r"((r)[0]), "=r"((r)[1]), "=r"((r)[2]), "=r"((r)[3]) : "r"(a))

#define LDSM_X4T(r, a)                                                         \
    asm volatile("ldmatrix.sync.aligned.m8n8.x4.trans.shared.b16 {%0,%1,%2,%3}, [%4];" \
                 : "=r"((r)[0]), "=r"((r)[1]), "=r"((r)[2]), "=r"((r)[3]) : "r"(a))

#define MMA16816(d, a, b0, b1)                                                 \
    asm volatile("mma.sync.aligned.m16n8k16.row.col.f32.f16.f16.f32 "          \
                 "{%0,%1,%2,%3}, {%4,%5,%6,%7}, {%8,%9}, {%0,%1,%2,%3};"       \
                 : "+f"((d)[0]), "+f"((d)[1]), "+f"((d)[2]), "+f"((d)[3])      \
                 : "r"((a)[0]), "r"((a)[1]), "r"((a)[2]), "r"((a)[3]),         \
                   "r"(b0), "r"(b1))

// ---------------------------- CSR construction ----------------------------

__global__ void count_deg_kernel(const int* __restrict__ dst, int* __restrict__ deg, int E) {
    int e = blockIdx.x * blockDim.x + threadIdx.x;
    if (e < E) atomicAdd(&deg[__ldg(&dst[e])], 1);
}

__global__ void scan_deg_kernel(const int* __restrict__ deg, int* __restrict__ rowptr,
                                int* __restrict__ cursor, float* __restrict__ invdeg, int n) {
    __shared__ int ssum[1024];
    int tid = threadIdx.x;
    int chunk = (n + 1023) / 1024;
    int lo = tid * chunk;
    int hi = lo + chunk; if (hi > n) hi = n;
    if (lo > n) lo = n;

    int sum = 0;
    for (int i = lo; i < hi; ++i) sum += deg[i];
    ssum[tid] = sum;
    __syncthreads();
    for (int off = 1; off < 1024; off <<= 1) {
        int v = (tid >= off) ? ssum[tid - off] : 0;
        __syncthreads();
        ssum[tid] += v;
        __syncthreads();
    }
    int run = ssum[tid] - sum;  // exclusive prefix
    for (int i = lo; i < hi; ++i) {
        rowptr[i] = run;
        cursor[i] = run;
        float d = (float)deg[i];
        invdeg[i] = 1.0f / fmaxf(d, 1.0f);
        run += deg[i];
    }
    if (tid == 1023) rowptr[n] = ssum[1023];
}

__global__ void fill_csr_kernel(const int* __restrict__ src, const int* __restrict__ dst,
                                int* __restrict__ cursor, int* __restrict__ colidx, int E) {
    int e = blockIdx.x * blockDim.x + threadIdx.x;
    if (e < E) {
        int d = __ldg(&dst[e]);
        int p = atomicAdd(&cursor[d], 1);
        colidx[p] = __ldg(&src[e]);
    }
}

// ------------------- standalone final aggregation + softmax ----------------
// warp per node; D=64. out = softmax(S + mean_j P[j]).

__global__ void aggregate_softmax(const __half* __restrict__ P, const float* __restrict__ S,
                                  const int* __restrict__ rowptr, const int* __restrict__ colidx,
                                  const float* __restrict__ invdeg, float* __restrict__ Y, int n) {
    int warp = (blockIdx.x * blockDim.x + threadIdx.x) >> 5;
    int lane = threadIdx.x & 31;
    int nwarps = (gridDim.x * blockDim.x) >> 5;

    for (int i = warp; i < n; i += nwarps) {
        int s = __ldg(&rowptr[i]);
        int e = __ldg(&rowptr[i + 1]);
        float inv = __ldg(&invdeg[i]);
        float2 acc = make_float2(0.f, 0.f);
        int j = s;
        for (; j + 7 < e; j += 8) {
            int c[8];
#pragma unroll
            for (int q = 0; q < 8; ++q) c[q] = __ldg(&colidx[j + q]);
#pragma unroll
            for (int q = 0; q < 8; ++q) {
                unsigned u = __ldg((const unsigned*)(P + (size_t)c[q] * 64) + lane);
                float2 f = __half22float2(*(const __half2*)&u);
                acc.x += f.x; acc.y += f.y;
            }
        }
        for (; j < e; ++j) {
            int c0 = __ldg(&colidx[j]);
            unsigned u = __ldg((const unsigned*)(P + (size_t)c0 * 64) + lane);
            float2 f = __half22float2(*(const __half2*)&u);
            acc.x += f.x; acc.y += f.y;
        }
        float2 sv = __ldg((const float2*)(S + (size_t)i * 64) + lane);
        float tx = fmaf(acc.x, inv, sv.x);
        float ty = fmaf(acc.y, inv, sv.y);
        float m = fmaxf(tx, ty);
#pragma unroll
        for (int o = 16; o; o >>= 1) m = fmaxf(m, __shfl_xor_sync(0xffffffffu, m, o));
        float ex = __expf(tx - m);
        float ey = __expf(ty - m);
        float sm = ex + ey;
#pragma unroll
        for (int o = 16; o; o >>= 1) sm += __shfl_xor_sync(0xffffffffu, sm, o);
        float rinv = 1.0f / sm;
        ((float2*)(Y + (size_t)i * 64))[lane] = make_float2(ex * rinv, ey * rinv);
    }
}

// ----------------------- standalone layer-1 GEMM ---------------------------
// C[64 x 128] = X[64 x 128] @ Wcat[:, colbase:+128]; fp32 X split in-kernel.

__global__ __launch_bounds__(256, 2) void gemm_l1(
    const float* __restrict__ A, const float* __restrict__ Ws,
    const float* __restrict__ Wn, const float* __restrict__ bias,
    float* __restrict__ S, __half* __restrict__ P, int n) {
    constexpr int K = 128, HF = 128;
    constexpr int LDA = 2 * K + 8;
    constexpr int LDB = 136;
    extern __shared__ __half smh[];
    __half* sA = smh;
    __half* sB = smh + 64 * LDA;

    int tid = threadIdx.x;
    int h = blockIdx.x & 1;          // nh = 2 column halves
    int colbase = h * 128;
    int t0 = blockIdx.x >> 1;
    int tstep = gridDim.x >> 1;

    for (int idx = tid; idx < K * 128; idx += 256) {
        int k = idx >> 7, c = idx & 127;
        int gc = colbase + c;
        float w = (gc < HF) ? __ldg(&Ws[k * HF + gc]) : __ldg(&Wn[k * HF + gc - HF]);
        __half wh = __float2half_rn(w);
        sB[k * LDB + c] = wh;
        sB[(K + k) * LDB + c] = __float2half_rn(w - __half2float(wh));
    }

    int lane = tid & 31;
    int warp = tid >> 5;
    int wm = warp & 3;
    int wnh = warp >> 2;
    int arow = wm * 16 + (lane & 15);
    int acolsel = (lane >> 4) * 8;
    int brow = lane & 15;
    int bcol = wnh * 64 + (lane >> 4) * 8;

    float2 binit[8];
#pragma unroll
    for (int nt = 0; nt < 8; ++nt) {
        int gc = colbase + wnh * 64 + nt * 8 + (lane & 3) * 2;
        float b0 = 0.f, b1 = 0.f;
        if (gc < HF) { b0 = __ldg(&bias[gc]); b1 = __ldg(&bias[gc + 1]); }
        binit[nt] = make_float2(b0, b1);
    }

    int ntiles = (n + 63) >> 6;
    for (int t = t0; t < ntiles; t += tstep) {
        int row0g = t * 64;
        __syncthreads();
        for (int idx = tid; idx < 64 * (K / 4); idx += 256) {
            int r  = idx / (K / 4);
            int k4 = idx % (K / 4);
            int gr = row0g + r;
            float4 v = make_float4(0.f, 0.f, 0.f, 0.f);
            if (gr < n) v = __ldg((const float4*)(A + (size_t)gr * K) + k4);
            __half h0 = __float2half_rn(v.x);
            __half h1 = __float2half_rn(v.y);
            __half h2 = __float2half_rn(v.z);
            __half h3 = __float2half_rn(v.w);
            __half2* ph = (__half2*)&sA[r * LDA + k4 * 4];
            ph[0] = __halves2half2(h0, h1);
            ph[1] = __halves2half2(h2, h3);
            __half2* pl = (__half2*)&sA[r * LDA + K + k4 * 4];
            pl[0] = __halves2half2(__float2half_rn(v.x - __half2float(h0)),
                                   __float2half_rn(v.y - __half2float(h1)));
            pl[1] = __halves2half2(__float2half_rn(v.z - __half2float(h2)),
                                   __float2half_rn(v.w - __half2float(h3)));
        }
        __syncthreads();

        float acc[8][4];
#pragma unroll
        for (int nt = 0; nt < 8; ++nt) {
            acc[nt][0] = binit[nt].x; acc[nt][1] = binit[nt].y;
            acc[nt][2] = binit[nt].x; acc[nt][3] = binit[nt].y;
        }
#pragma unroll
        for (int k16 = 0; k16 < K; k16 += 16) {
            unsigned ah[4], al[4];
            LDSM_X4(ah, su32(&sA[arow * LDA + k16 + acolsel]));
            LDSM_X4(al, su32(&sA[arow * LDA + K + k16 + acolsel]));
#pragma unroll
            for (int tt = 0; tt < 4; ++tt) {
                unsigned bh[4], bl[4];
                LDSM_X4T(bh, su32(&sB[(k16 + brow) * LDB + bcol + tt * 16]));
                MMA16816(acc[tt * 2],     ah, bh[0], bh[1]);
                MMA16816(acc[tt * 2 + 1], ah, bh[2], bh[3]);
                MMA16816(acc[tt * 2],     al, bh[0], bh[1]);
                MMA16816(acc[tt * 2 + 1], al, bh[2], bh[3]);
                LDSM_X4T(bl, su32(&sB[(K + k16 + brow) * LDB + bcol + tt * 16]));
                MMA16816(acc[tt * 2],     ah, bl[0], bl[1]);
                MMA16816(acc[tt * 2 + 1], ah, bl[2], bl[3]);
            }
        }

        int r0 = row0g + wm * 16 + (lane >> 2);
#pragma unroll
        for (int nt = 0; nt < 8; ++nt) {
            int gc = colbase + wnh * 64 + nt * 8 + (lane & 3) * 2;
            if (gc < HF) {
                if (r0 < n)
                    *(float2*)(S + (size_t)r0 * HF + gc) = make_float2(acc[nt][0], acc[nt][1]);
                if (r0 + 8 < n)
                    *(float2*)(S + (size_t)(r0 + 8) * HF + gc) = make_float2(acc[nt][2], acc[nt][3]);
            } else {
                int pc = gc - HF;
                if (r0 < n)
                    *(__half2*)(P + (size_t)r0 * HF + pc) = __floats2half2_rn(acc[nt][0], acc[nt][1]);
                if (r0 + 8 < n)
                    *(__half2*)(P + (size_t)(r0 + 8) * HF + pc) = __floats2half2_rn(acc[nt][2], acc[nt][3]);
            }
        }
    }
}

// ------------------ FUSED aggregate + next-layer projection ----------------
// Per 64-row tile: (a) each warp aggregates 8 nodes (mean of neighbor P rows,
// + S, relu), splits hi/lo fp16 straight into the MMA A tile in SMEM;
// (b) MMA with [Ws|Wn] (K = input width, output 2x64 cols: S fp32 | P fp16).

template <int K>
__global__ __launch_bounds__(256, 2) void fused_agg_gemm(
    const __half* __restrict__ Pin, const float* __restrict__ Sin,
    const int* __restrict__ rowptr, const int* __restrict__ colidx,
    const float* __restrict__ invdeg,
    const float* __restrict__ Ws, const float* __restrict__ Wn,
    const float* __restrict__ bias,
    float* __restrict__ Sout, __half* __restrict__ Pout, int n) {
    constexpr int HF = 64;
    constexpr int LDA = 2 * K + 8;
    constexpr int LDB = 136;
    extern __shared__ __half smh[];
    __half* sA = smh;                 // [64][LDA]
    __half* sB = smh + 64 * LDA;      // [2K][LDB]

    int tid = threadIdx.x;
    int lane = tid & 31;
    int warp = tid >> 5;

    // ---- W load + hi/lo split (once) ----
    for (int idx = tid; idx < K * 128; idx += 256) {
        int k = idx >> 7, c = idx & 127;
        float w = (c < HF) ? __ldg(&Ws[k * HF + c]) : __ldg(&Wn[k * HF + c - HF]);
        __half wh = __float2half_rn(w);
        sB[k * LDB + c] = wh;
        sB[(K + k) * LDB + c] = __float2half_rn(w - __half2float(wh));
    }

    int wm = warp & 3;
    int wnh = warp >> 2;
    int arow = wm * 16 + (lane & 15);
    int acolsel = (lane >> 4) * 8;
    int brow = lane & 15;
    int bcol = wnh * 64 + (lane >> 4) * 8;

    float2 binit[8];
#pragma unroll
    for (int nt = 0; nt < 8; ++nt) {
        int gc = wnh * 64 + nt * 8 + (lane & 3) * 2;
        float b0 = 0.f, b1 = 0.f;
        if (gc < HF) { b0 = __ldg(&bias[gc]); b1 = __ldg(&bias[gc + 1]); }
        binit[nt] = make_float2(b0, b1);
    }

    int ntiles = (n + 63) >> 6;
    for (int t = blockIdx.x; t < ntiles; t += gridDim.x) {
        int row0 = t * 64;
        __syncthreads();   // sA reuse

        // ---- phase (a): aggregate 8 nodes per warp into sA (split fp16) ----
#pragma unroll 1
        for (int r8 = 0; r8 < 8; ++r8) {
            int r = warp * 8 + r8;
            int i = row0 + r;
            if (K == 128) {
                float4 acc = make_float4(0.f, 0.f, 0.f, 0.f);
                float ox = 0.f, oy = 0.f, oz = 0.f, ow = 0.f;
                if (i < n) {
                    int s = __ldg(&rowptr[i]);
                    int e = __ldg(&rowptr[i + 1]);
                    float inv = __ldg(&invdeg[i]);
                    int j = s;
                    for (; j + 7 < e; j += 8) {
                        int c[8];
#pragma unroll
                        for (int q = 0; q < 8; ++q) c[q] = __ldg(&colidx[j + q]);
#pragma unroll
                        for (int q = 0; q < 8; ++q) {
                            uint2 u = __ldg((const uint2*)(Pin + (size_t)c[q] * 128) + lane);
                            float2 a = __half22float2(*(const __half2*)&u.x);
                            float2 b = __half22float2(*(const __half2*)&u.y);
                            acc.x += a.x; acc.y += a.y; acc.z += b.x; acc.w += b.y;
                        }
                    }
                    for (; j < e; ++j) {
                        int c0 = __ldg(&colidx[j]);
                        uint2 u = __ldg((const uint2*)(Pin + (size_t)c0 * 128) + lane);
                        float2 a = __half22float2(*(const __half2*)&u.x);
                        float2 b = __half22float2(*(const __half2*)&u.y);
                        acc.x += a.x; acc.y += a.y; acc.z += b.x; acc.w += b.y;
                    }
                    float4 sv = __ldg((const float4*)(Sin + (size_t)i * 128) + lane);
                    ox = fmaxf(fmaf(acc.x, inv, sv.x), 0.f);
                    oy = fmaxf(fmaf(acc.y, inv, sv.y), 0.f);
                    oz = fmaxf(fmaf(acc.z, inv, sv.z), 0.f);
                    ow = fmaxf(fmaf(acc.w, inv, sv.w), 0.f);
                }
                __half hx = __float2half_rn(ox), hy = __float2half_rn(oy);
                __half hz = __float2half_rn(oz), hw = __float2half_rn(ow);
                __half2 hi01 = __halves2half2(hx, hy), hi23 = __halves2half2(hz, hw);
                __half2 lo01 = __halves2half2(__float2half_rn(ox - __half2float(hx)),
                                              __float2half_rn(oy - __half2float(hy)));
                __half2 lo23 = __halves2half2(__float2half_rn(oz - __half2float(hz)),
                                              __float2half_rn(ow - __half2float(hw)));
                *(uint2*)&sA[r * LDA + 4 * lane] =
                    make_uint2(*(unsigned*)&hi01, *(unsigned*)&hi23);
                *(uint2*)&sA[r * LDA + 128 + 4 * lane] =
                    make_uint2(*(unsigned*)&lo01, *(unsigned*)&lo23);
            } else {  // K == 64
                float2 acc = make_float2(0.f, 0.f);
                float ox = 0.f, oy = 0.f;
                if (i < n) {
                    int s = __ldg(&rowptr[i]);
                    int e = __ldg(&rowptr[i + 1]);
                    float inv = __ldg(&invdeg[i]);
                    int j = s;
                    for (; j + 7 < e; j += 8) {
                        int c[8];
#pragma unroll
                        for (int q = 0; q < 8; ++q) c[q] = __ldg(&colidx[j + q]);
#pragma unroll
                        for (int q = 0; q < 8; ++q) {
                            unsigned u = __ldg((const unsigned*)(Pin + (size_t)c[q] * 64) + lane);
                            float2 f = __half22float2(*(const __half2*)&u);
                            acc.x += f.x; acc.y += f.y;
                        }
                    }
                    for (; j < e; ++j) {
                        int c0 = __ldg(&colidx[j]);
                        unsigned u = __ldg((const unsigned*)(Pin + (size_t)c0 * 64) + lane);
                        float2 f = __half22float2(*(const __half2*)&u);
                        acc.x += f.x; acc.y += f.y;
                    }
                    float2 sv = __ldg((const float2*)(Sin + (size_t)i * 64) + lane);
                    ox = fmaxf(fmaf(acc.x, inv, sv.x), 0.f);
                    oy = fmaxf(fmaf(acc.y, inv, sv.y), 0.f);
                }
                __half hx = __float2half_rn(ox), hy = __float2half_rn(oy);
                __half2 hp = __halves2half2(hx, hy);
                __half2 lp = __halves2half2(__float2half_rn(ox - __half2float(hx)),
                                            __float2half_rn(oy - __half2float(hy)));
                *(unsigned*)&sA[r * LDA + 2 * lane] = *(unsigned*)&hp;
                *(unsigned*)&sA[r * LDA + 64 + 2 * lane] = *(unsigned*)&lp;
            }
        }
        __syncthreads();

        // ---- phase (b): MMA + epilogue ----
        float acc[8][4];
#pragma unroll
        for (int nt = 0; nt < 8; ++nt) {
            acc[nt][0] = binit[nt].x; acc[nt][1] = binit[nt].y;
            acc[nt][2] = binit[nt].x; acc[nt][3] = binit[nt].y;
        }
#pragma unroll
        for (int k16 = 0; k16 < K; k16 += 16) {
            unsigned ah[4], al[4];
            LDSM_X4(ah, su32(&sA[arow * LDA + k16 + acolsel]));
            LDSM_X4(al, su32(&sA[arow * LDA + K + k16 + acolsel]));
#pragma unroll
            for (int tt = 0; tt < 4; ++tt) {
                unsigned bh[4], bl[4];
                LDSM_X4T(bh, su32(&sB[(k16 + brow) * LDB + bcol + tt * 16]));
                MMA16816(acc[tt * 2],     ah, bh[0], bh[1]);
                MMA16816(acc[tt * 2 + 1], ah, bh[2], bh[3]);
                MMA16816(acc[tt * 2],     al, bh[0], bh[1]);
                MMA16816(acc[tt * 2 + 1], al, bh[2], bh[3]);
                LDSM_X4T(bl, su32(&sB[(K + k16 + brow) * LDB + bcol + tt * 16]));
                MMA16816(acc[tt * 2],     ah, bl[0], bl[1]);
                MMA16816(acc[tt * 2 + 1], ah, bl[2], bl[3]);
            }
        }

        int r0 = row0 + wm * 16 + (lane >> 2);
#pragma unroll
        for (int nt = 0; nt < 8; ++nt) {
            int gc = wnh * 64 + nt * 8 + (lane & 3) * 2;
            if (gc < HF) {
                if (r0 < n)
                    *(float2*)(Sout + (size_t)r0 * HF + gc) = make_float2(acc[nt][0], acc[nt][1]);
                if (r0 + 8 < n)
                    *(float2*)(Sout + (size_t)(r0 + 8) * HF + gc) = make_float2(acc[nt][2], acc[nt][3]);
            } else {
                int pc = gc - HF;
                if (r0 < n)
                    *(__half2*)(Pout + (size_t)r0 * HF + pc) = __floats2half2_rn(acc[nt][0], acc[nt][1]);
                if (r0 + 8 < n)
                    *(__half2*)(Pout + (size_t)(r0 + 8) * HF + pc) = __floats2half2_rn(acc[nt][2], acc[nt][3]);
            }
        }
    }
}

// ---------------------------------------------------------------------------

extern "C" void kernel_launch(void* const* d_in, const int* in_sizes, int n_in,
                              void* d_out, int out_size) {
    const float* x   = (const float*)d_in[0];
    const int*   src = (const int*)d_in[1];
    const int*   dst = (const int*)d_in[2];
    const float* ws1 = (const float*)d_in[3];
    const float* wn1 = (const float*)d_in[4];
    const float* b1  = (const float*)d_in[5];
    const float* ws2 = (const float*)d_in[6];
    const float* wn2 = (const float*)d_in[7];
    const float* b2  = (const float*)d_in[8];
    const float* ws3 = (const float*)d_in[9];
    const float* wn3 = (const float*)d_in[10];
    const float* b3  = (const float*)d_in[11];
    float* out = (float*)d_out;

    int N = in_sizes[0] / 128;
    int E = in_sizes[1];

    int *deg, *rowptr, *cursor, *colidx;
    float *invdeg, *S1;
    __half *P1, *buf2;
    cudaGetSymbolAddress((void**)&deg,    g_deg);
    cudaGetSymbolAddress((void**)&rowptr, g_rowptr);
    cudaGetSymbolAddress((void**)&cursor, g_cursor);
    cudaGetSymbolAddress((void**)&colidx, g_colidx);
    cudaGetSymbolAddress((void**)&invdeg, g_invdeg);
    cudaGetSymbolAddress((void**)&S1,     g_S);
    cudaGetSymbolAddress((void**)&P1,     g_P);
    cudaGetSymbolAddress((void**)&buf2,   g_buf2);

    // S2 (fp32, w64) and P2 (fp16, w64) carved out of g_buf2
    float*  S2 = (float*)buf2;                       // MAXN*64 floats
    __half* P2 = buf2 + (size_t)MAXN * 128;          // MAXN*64 halves
    // layer-3 outputs reuse g_S / g_P (S1/P1 dead by then)
    float*  S3 = S1;
    __half* P3 = P1;

    const int SMEM_K128 = (64 * (2 * 128 + 8) + 2 * 128 * 136) * 2;  // 103424
    const int SMEM_K64  = (64 * (2 * 64 + 8) + 2 * 64 * 136) * 2;    //  52224
    cudaFuncSetAttribute((const void*)gemm_l1,
                         cudaFuncAttributeMaxDynamicSharedMemorySize, SMEM_K128);
    cudaFuncSetAttribute((const void*)fused_agg_gemm<128>,
                         cudaFuncAttributeMaxDynamicSharedMemorySize, SMEM_K128);
    cudaFuncSetAttribute((const void*)fused_agg_gemm<64>,
                         cudaFuncAttributeMaxDynamicSharedMemorySize, SMEM_K64);

    static cudaStream_t s_csr = 0;
    static cudaEvent_t e_fork = 0, e_join = 0;
    if (!s_csr) {
        cudaStreamCreateWithFlags(&s_csr, cudaStreamNonBlocking);
        cudaEventCreateWithFlags(&e_fork, cudaEventDisableTiming);
        cudaEventCreateWithFlags(&e_join, cudaEventDisableTiming);
    }

    // ---- fork: CSR build on side stream ----
    cudaEventRecord(e_fork, 0);
    cudaStreamWaitEvent(s_csr, e_fork, 0);
    cudaMemsetAsync(deg, 0, N * sizeof(int), s_csr);
    count_deg_kernel<<<(E + 255) / 256, 256, 0, s_csr>>>(dst, deg, E);
    scan_deg_kernel<<<1, 1024, 0, s_csr>>>(deg, rowptr, cursor, invdeg, N);
    fill_csr_kernel<<<(E + 255) / 256, 256, 0, s_csr>>>(src, dst, cursor, colidx, E);
    cudaEventRecord(e_join, s_csr);

    // ---- layer 1: X -> [S1 | P1] (both width 128) ----
    gemm_l1<<<296, 256, SMEM_K128>>>(x, ws1, wn1, b1, S1, P1, N);
    cudaStreamWaitEvent(0, e_join, 0);

    // ---- fused layer 2: agg(P1)+S1 -> relu -> @[Ws2|Wn2] -> S2,P2 ----
    fused_agg_gemm<128><<<296, 256, SMEM_K128>>>(P1, S1, rowptr, colidx, invdeg,
                                                 ws2, wn2, b2, S2, P2, N);
    // ---- fused layer 3: agg(P2)+S2 -> relu -> @[Ws3|Wn3] -> S3,P3 ----
    fused_agg_gemm<64><<<296, 256, SMEM_K64>>>(P2, S2, rowptr, colidx, invdeg,
                                               ws3, wn3, b3, S3, P3, N);
    // ---- final: softmax(S3 + agg(P3)) -> out ----
    aggregate_softmax<<<2048, 256>>>(P3, S3, rowptr, colidx, invdeg, out, N);
}

// round 10
// speedup vs baseline: 1.3397x; 1.3397x over previous
#include <cuda_runtime.h>
#include <cuda_fp16.h>
#include <cuda_bf16.h>
#include <math.h>

// ---------------------------------------------------------------------------
// GraphSAGE (3x SAGEConv mean + ReLU, softmax) on GB300 — round 10.
//  * Round-8 structure (best: 440.5us) with 2-phase GEMM:
//    A plain fp16, W split hi|lo:  A@W ~= Ah*Wh + Ah*Wl  (al*Wh dropped).
//    -> 2/3 tensor work, half the A smem/copy, h stored plain fp16.
//  * Aggregation + CSR overlap unchanged from round 8.
// ---------------------------------------------------------------------------

#define MAXN 100000
#define MAXE 1600000

__device__ int    g_deg[MAXN];
__device__ int    g_rowptr[MAXN + 1];
__device__ int    g_cursor[MAXN];
__device__ int    g_colidx[MAXE];
__device__ float  g_invdeg[MAXN];
__device__ float  g_S[(size_t)MAXN * 128];       // self-projection (+bias), fp32
__device__ __half g_P[(size_t)MAXN * 128];       // neighbor-projection, fp16
__device__ __half g_h[(size_t)MAXN * 128];       // hidden activations, fp16

static __device__ __forceinline__ unsigned su32(const void* p) {
    return (unsigned)__cvta_generic_to_shared(p);
}

#define LDSM_X4(r, a)                                                          \
    asm volatile("ldmatrix.sync.aligned.m8n8.x4.shared.b16 {%0,%1,%2,%3}, [%4];" \
                 : "=r"((r)[0]), "=r"((r)[1]), "=r"((r)[2]), "=r"((r)[3]) : "r"(a))

#define LDSM_X4T(r, a)                                                         \
    asm volatile("ldmatrix.sync.aligned.m8n8.x4.trans.shared.b16 {%0,%1,%2,%3}, [%4];" \
                 : "=r"((r)[0]), "=r"((r)[1]), "=r"((r)[2]), "=r"((r)[3]) : "r"(a))

#define MMA16816(d, a, b0, b1)                                                 \
    asm volatile("mma.sync.aligned.m16n8k16.row.col.f32.f16.f16.f32 "          \
                 "{%0,%1,%2,%3}, {%4,%5,%6,%7}, {%8,%9}, {%0,%1,%2,%3};"       \
                 : "+f"((d)[0]), "+f"((d)[1]), "+f"((d)[2]), "+f"((d)[3])      \
                 : "r"((a)[0]), "r"((a)[1]), "r"((a)[2]), "r"((a)[3]),         \
                   "r"(b0), "r"(b1))

// ---------------------------- CSR construction ----------------------------

__global__ void count_deg_kernel(const int* __restrict__ dst, int* __restrict__ deg, int E) {
    int e = blockIdx.x * blockDim.x + threadIdx.x;
    if (e < E) atomicAdd(&deg[__ldg(&dst[e])], 1);
}

__global__ void scan_deg_kernel(const int* __restrict__ deg, int* __restrict__ rowptr,
                                int* __restrict__ cursor, float* __restrict__ invdeg, int n) {
    __shared__ int ssum[1024];
    int tid = threadIdx.x;
    int chunk = (n + 1023) / 1024;
    int lo = tid * chunk;
    int hi = lo + chunk; if (hi > n) hi = n;
    if (lo > n) lo = n;

    int sum = 0;
    for (int i = lo; i < hi; ++i) sum += deg[i];
    ssum[tid] = sum;
    __syncthreads();
    for (int off = 1; off < 1024; off <<= 1) {
        int v = (tid >= off) ? ssum[tid - off] : 0;
        __syncthreads();
        ssum[tid] += v;
        __syncthreads();
    }
    int run = ssum[tid] - sum;  // exclusive prefix
    for (int i = lo; i < hi; ++i) {
        rowptr[i] = run;
        cursor[i] = run;
        float d = (float)deg[i];
        invdeg[i] = 1.0f / fmaxf(d, 1.0f);
        run += deg[i];
    }
    if (tid == 1023) rowptr[n] = ssum[1023];
}

__global__ void fill_csr_kernel(const int* __restrict__ src, const int* __restrict__ dst,
                                int* __restrict__ cursor, int* __restrict__ colidx, int E) {
    int e = blockIdx.x * blockDim.x + threadIdx.x;
    if (e < E) {
        int d = __ldg(&dst[e]);
        int p = atomicAdd(&cursor[d], 1);
        colidx[p] = __ldg(&src[e]);
    }
}

// ------------------- aggregation (mean) with fused epilogue ----------------
// warp per node. t = S[i] + mean_j P[j]  (P fp16, fp32 accumulate)
// ACT 0: Y = relu(t) stored fp16, row width D.
// ACT 1: Y = softmax(t) stored fp32, row width D (D==64 only).

template <int D, int ACT>
__global__ void aggregate_ep(const __half* __restrict__ P, const float* __restrict__ S,
                             const int* __restrict__ rowptr, const int* __restrict__ colidx,
                             const float* __restrict__ invdeg, void* __restrict__ Yv, int n) {
    int warp = (blockIdx.x * blockDim.x + threadIdx.x) >> 5;
    int lane = threadIdx.x & 31;
    int nwarps = (gridDim.x * blockDim.x) >> 5;

    for (int i = warp; i < n; i += nwarps) {
        int s = __ldg(&rowptr[i]);
        int e = __ldg(&rowptr[i + 1]);
        float inv = __ldg(&invdeg[i]);

        if (D == 128) {
            float4 acc = make_float4(0.f, 0.f, 0.f, 0.f);
            int j = s;
            for (; j + 7 < e; j += 8) {
                int c[8];
#pragma unroll
                for (int q = 0; q < 8; ++q) c[q] = __ldg(&colidx[j + q]);
#pragma unroll
                for (int q = 0; q < 8; ++q) {
                    uint2 u = __ldg((const uint2*)(P + (size_t)c[q] * 128) + lane);
                    float2 a = __half22float2(*(const __half2*)&u.x);
                    float2 b = __half22float2(*(const __half2*)&u.y);
                    acc.x += a.x; acc.y += a.y; acc.z += b.x; acc.w += b.y;
                }
            }
            for (; j < e; ++j) {
                int c0 = __ldg(&colidx[j]);
                uint2 u = __ldg((const uint2*)(P + (size_t)c0 * 128) + lane);
                float2 a = __half22float2(*(const __half2*)&u.x);
                float2 b = __half22float2(*(const __half2*)&u.y);
                acc.x += a.x; acc.y += a.y; acc.z += b.x; acc.w += b.y;
            }
            float4 sv = __ldg((const float4*)(S + (size_t)i * 128) + lane);
            float ox = fmaxf(fmaf(acc.x, inv, sv.x), 0.f);
            float oy = fmaxf(fmaf(acc.y, inv, sv.y), 0.f);
            float oz = fmaxf(fmaf(acc.z, inv, sv.z), 0.f);
            float ow = fmaxf(fmaf(acc.w, inv, sv.w), 0.f);
            __half2 p01 = __floats2half2_rn(ox, oy);
            __half2 p23 = __floats2half2_rn(oz, ow);
            *(uint2*)((__half*)Yv + (size_t)i * 128 + 4 * lane) =
                make_uint2(*(unsigned*)&p01, *(unsigned*)&p23);
        } else {  // D == 64
            float2 acc = make_float2(0.f, 0.f);
            int j = s;
            for (; j + 7 < e; j += 8) {
                int c[8];
#pragma unroll
                for (int q = 0; q < 8; ++q) c[q] = __ldg(&colidx[j + q]);
#pragma unroll
                for (int q = 0; q < 8; ++q) {
                    unsigned u = __ldg((const unsigned*)(P + (size_t)c[q] * 64) + lane);
                    float2 f = __half22float2(*(const __half2*)&u);
                    acc.x += f.x; acc.y += f.y;
                }
            }
            for (; j < e; ++j) {
                int c0 = __ldg(&colidx[j]);
                unsigned u = __ldg((const unsigned*)(P + (size_t)c0 * 64) + lane);
                float2 f = __half22float2(*(const __half2*)&u);
                acc.x += f.x; acc.y += f.y;
            }
            float2 sv = __ldg((const float2*)(S + (size_t)i * 64) + lane);
            float tx = fmaf(acc.x, inv, sv.x);
            float ty = fmaf(acc.y, inv, sv.y);
            if (ACT == 0) {
                __half2 hp = __floats2half2_rn(fmaxf(tx, 0.f), fmaxf(ty, 0.f));
                *(unsigned*)((__half*)Yv + (size_t)i * 64 + 2 * lane) = *(unsigned*)&hp;
            } else {
                float m = fmaxf(tx, ty);
#pragma unroll
                for (int o = 16; o; o >>= 1) m = fmaxf(m, __shfl_xor_sync(0xffffffffu, m, o));
                float ex = __expf(tx - m);
                float ey = __expf(ty - m);
                float sm = ex + ey;
#pragma unroll
                for (int o = 16; o; o >>= 1) sm += __shfl_xor_sync(0xffffffffu, sm, o);
                float rinv = 1.0f / sm;
                ((float2*)((float*)Yv + (size_t)i * 64))[lane] = make_float2(ex * rinv, ey * rinv);
            }
        }
    }
}

// ----------------------- tensor-core projection GEMM -----------------------
// 2-phase split: C = Ah*Wh + Ah*Wl (fp32 accum). A plain fp16 (width K);
// sB holds Wh rows [0..K) and Wl rows [K..2K). 2 CTAs/SM give overlap.
// PREHALF: A already fp16 (raw copy). Else fp32, rounded in-kernel.

template <int K, bool PREHALF>
__global__ __launch_bounds__(256, 2) void gemm_mma(
    const void* __restrict__ Av, const float* __restrict__ Ws,
    const float* __restrict__ Wn, const float* __restrict__ bias,
    float* __restrict__ S, __half* __restrict__ P,
    int n, int HF, int nh) {
    constexpr int LDA = K + 8;
    constexpr int LDB = 136;
    extern __shared__ __half smh[];
    __half* sA = smh;                 // [64][LDA]
    __half* sB = smh + 64 * LDA;      // [2K][LDB]  (Wh rows, Wl rows)

    int tid = threadIdx.x;
    int h = blockIdx.x % nh;
    int colbase = h * 128;
    int t0 = blockIdx.x / nh;
    int tstep = gridDim.x / nh;

    // ---- W load + hi/lo split (once per block) ----
    for (int idx = tid; idx < K * 128; idx += 256) {
        int k = idx >> 7, c = idx & 127;
        int gc = colbase + c;
        float w = (gc < HF) ? __ldg(&Ws[k * HF + gc]) : __ldg(&Wn[k * HF + gc - HF]);
        __half wh = __float2half_rn(w);
        sB[k * LDB + c] = wh;
        sB[(K + k) * LDB + c] = __float2half_rn(w - __half2float(wh));
    }

    int lane = tid & 31;
    int warp = tid >> 5;
    int wm = warp & 3;
    int wnh = warp >> 2;

    int arow = wm * 16 + (lane & 15);
    int acolsel = (lane >> 4) * 8;
    int brow = lane & 15;
    int bcol = wnh * 64 + (lane >> 4) * 8;

    float2 binit[8];
#pragma unroll
    for (int nt = 0; nt < 8; ++nt) {
        int gc = colbase + wnh * 64 + nt * 8 + (lane & 3) * 2;
        float b0 = 0.f, b1 = 0.f;
        if (gc < HF) { b0 = __ldg(&bias[gc]); b1 = __ldg(&bias[gc + 1]); }
        binit[nt] = make_float2(b0, b1);
    }

    int ntiles = (n + 63) >> 6;
    for (int t = t0; t < ntiles; t += tstep) {
        int row0g = t * 64;
        __syncthreads();

        if (PREHALF) {
            constexpr int CPR = K / 8;   // uint4 chunks per row
            const __half* A = (const __half*)Av;
            for (int idx = tid; idx < 64 * CPR; idx += 256) {
                int r = idx / CPR, c = idx % CPR;
                int gr = row0g + r;
                uint4 v = make_uint4(0u, 0u, 0u, 0u);
                if (gr < n) v = __ldg((const uint4*)(A + (size_t)gr * K) + c);
                *(uint4*)&sA[r * LDA + c * 8] = v;
            }
        } else {
            const float* A = (const float*)Av;
            for (int idx = tid; idx < 64 * (K / 4); idx += 256) {
                int r  = idx / (K / 4);
                int k4 = idx % (K / 4);
                int gr = row0g + r;
                float4 v = make_float4(0.f, 0.f, 0.f, 0.f);
                if (gr < n) v = __ldg((const float4*)(A + (size_t)gr * K) + k4);
                __half2* ph = (__half2*)&sA[r * LDA + k4 * 4];
                ph[0] = __floats2half2_rn(v.x, v.y);
                ph[1] = __floats2half2_rn(v.z, v.w);
            }
        }
        __syncthreads();

        float acc[8][4];
#pragma unroll
        for (int nt = 0; nt < 8; ++nt) {
            acc[nt][0] = binit[nt].x; acc[nt][1] = binit[nt].y;
            acc[nt][2] = binit[nt].x; acc[nt][3] = binit[nt].y;
        }

        // ---- 2-phase K sweep: Ah loaded once; Wh then Wl ----
#pragma unroll
        for (int k16 = 0; k16 < K; k16 += 16) {
            unsigned ah[4];
            LDSM_X4(ah, su32(&sA[arow * LDA + k16 + acolsel]));
#pragma unroll
            for (int tt = 0; tt < 4; ++tt) {
                unsigned bh[4], bl[4];
                LDSM_X4T(bh, su32(&sB[(k16 + brow) * LDB + bcol + tt * 16]));
                MMA16816(acc[tt * 2],     ah, bh[0], bh[1]);
                MMA16816(acc[tt * 2 + 1], ah, bh[2], bh[3]);
                LDSM_X4T(bl, su32(&sB[(K + k16 + brow) * LDB + bcol + tt * 16]));
                MMA16816(acc[tt * 2],     ah, bl[0], bl[1]);
                MMA16816(acc[tt * 2 + 1], ah, bl[2], bl[3]);
            }
        }

        // ---- epilogue: S fp32 / P fp16 ----
        int r0 = row0g + wm * 16 + (lane >> 2);
#pragma unroll
        for (int nt = 0; nt < 8; ++nt) {
            int gc = colbase + wnh * 64 + nt * 8 + (lane & 3) * 2;
            if (gc < HF) {
                if (r0 < n)
                    *(float2*)(S + (size_t)r0 * HF + gc) = make_float2(acc[nt][0], acc[nt][1]);
                if (r0 + 8 < n)
                    *(float2*)(S + (size_t)(r0 + 8) * HF + gc) = make_float2(acc[nt][2], acc[nt][3]);
            } else {
                int pc = gc - HF;
                if (r0 < n)
                    *(__half2*)(P + (size_t)r0 * HF + pc) = __floats2half2_rn(acc[nt][0], acc[nt][1]);
                if (r0 + 8 < n)
                    *(__half2*)(P + (size_t)(r0 + 8) * HF + pc) = __floats2half2_rn(acc[nt][2], acc[nt][3]);
            }
        }
    }
}

// ---------------------------------------------------------------------------

extern "C" void kernel_launch(void* const* d_in, const int* in_sizes, int n_in,
                              void* d_out, int out_size) {
    const float* x   = (const float*)d_in[0];
    const int*   src = (const int*)d_in[1];
    const int*   dst = (const int*)d_in[2];
    const float* ws1 = (const float*)d_in[3];
    const float* wn1 = (const float*)d_in[4];
    const float* b1  = (const float*)d_in[5];
    const float* ws2 = (const float*)d_in[6];
    const float* wn2 = (const float*)d_in[7];
    const float* b2  = (const float*)d_in[8];
    const float* ws3 = (const float*)d_in[9];
    const float* wn3 = (const float*)d_in[10];
    const float* b3  = (const float*)d_in[11];
    float* out = (float*)d_out;

    int N = in_sizes[0] / 128;
    int E = in_sizes[1];

    int *deg, *rowptr, *cursor, *colidx;
    float *invdeg, *Sb;
    __half *Pb, *hs;
    cudaGetSymbolAddress((void**)&deg,    g_deg);
    cudaGetSymbolAddress((void**)&rowptr, g_rowptr);
    cudaGetSymbolAddress((void**)&cursor, g_cursor);
    cudaGetSymbolAddress((void**)&colidx, g_colidx);
    cudaGetSymbolAddress((void**)&invdeg, g_invdeg);
    cudaGetSymbolAddress((void**)&Sb,     g_S);
    cudaGetSymbolAddress((void**)&Pb,     g_P);
    cudaGetSymbolAddress((void**)&hs,     g_h);

    const int SMEM_K128 = (64 * (128 + 8) + 2 * 128 * 136) * 2;  // 87040
    const int SMEM_K64  = (64 * (64 + 8) + 2 * 64 * 136) * 2;    // 44032
    cudaFuncSetAttribute((const void*)gemm_mma<128, false>,
                         cudaFuncAttributeMaxDynamicSharedMemorySize, SMEM_K128);
    cudaFuncSetAttribute((const void*)gemm_mma<128, true>,
                         cudaFuncAttributeMaxDynamicSharedMemorySize, SMEM_K128);
    cudaFuncSetAttribute((const void*)gemm_mma<64, true>,
                         cudaFuncAttributeMaxDynamicSharedMemorySize, SMEM_K64);

    static cudaStream_t s_csr = 0;
    static cudaEvent_t e_fork = 0, e_join = 0;
    if (!s_csr) {
        cudaStreamCreateWithFlags(&s_csr, cudaStreamNonBlocking);
        cudaEventCreateWithFlags(&e_fork, cudaEventDisableTiming);
        cudaEventCreateWithFlags(&e_join, cudaEventDisableTiming);
    }

    // ---- fork: CSR build on side stream ----
    cudaEventRecord(e_fork, 0);
    cudaStreamWaitEvent(s_csr, e_fork, 0);
    cudaMemsetAsync(deg, 0, N * sizeof(int), s_csr);
    count_deg_kernel<<<(E + 255) / 256, 256, 0, s_csr>>>(dst, deg, E);
    scan_deg_kernel<<<1, 1024, 0, s_csr>>>(deg, rowptr, cursor, invdeg, N);
    fill_csr_kernel<<<(E + 255) / 256, 256, 0, s_csr>>>(src, dst, cursor, colidx, E);
    cudaEventRecord(e_join, s_csr);

    // ---- main: layer-1 GEMM (fp32 X, rounded in-kernel) ----
    gemm_mma<128, false><<<296, 256, SMEM_K128>>>(x, ws1, wn1, b1, Sb, Pb, N, 128, 2);
    cudaStreamWaitEvent(0, e_join, 0);

    const int AGG_BLOCKS = 2048;

    // ---- layer 1 ----
    aggregate_ep<128, 0><<<AGG_BLOCKS, 256>>>(Pb, Sb, rowptr, colidx, invdeg, hs, N);
    // ---- layer 2 ----
    gemm_mma<128, true><<<296, 256, SMEM_K128>>>(hs, ws2, wn2, b2, Sb, Pb, N, 64, 1);
    aggregate_ep<64, 0><<<AGG_BLOCKS, 256>>>(Pb, Sb, rowptr, colidx, invdeg, hs, N);
    // ---- layer 3 ----
    gemm_mma<64, true><<<296, 256, SMEM_K64>>>(hs, ws3, wn3, b3, Sb, Pb, N, 64, 1);
    aggregate_ep<64, 1><<<AGG_BLOCKS, 256>>>(Pb, Sb, rowptr, colidx, invdeg, out, N);
}